// round 4
// baseline (speedup 1.0000x reference)
#include <cuda_runtime.h>

#define NN 100000
#define NE 1600000
#define DD 128
#define NG 64
#define NL 7
#define LEAKY 0.01f
#define BN_EPS 1e-5f

// ---------------- scratch (static device globals; no allocation) ----------------
__device__ __align__(16) float  g_T[(size_t)NN * DD];     // GEMM output (messages source)
__device__ __align__(16) float  g_AGG[(size_t)NN * DD];   // aggregated (pre-activation)
__device__ int    g_cnt[NN];                // histogram, then reused as fill cursor
__device__ int    g_rowptr[NN + 1];
__device__ int    g_col[NE];
__device__ float  g_w[NE];
__device__ float  g_dinv[NN];
__device__ double g_sum[DD], g_sq[DD];
__device__ __align__(16) float  g_Wf[DD * DD];            // BN-folded weights for next layer
__device__ float  g_bf[DD];
__device__ float  g_a[DD], g_c[DD];         // last-layer BN affine
__device__ float  g_pool[NG * DD];
__device__ float  g_pcnt[NG];
__device__ int    g_is64_ei, g_is64_batch;  // input index dtype flags

__device__ __forceinline__ float leaky_f(float v) { return v > 0.f ? v : LEAKY * v; }

__device__ __forceinline__ int load_idx(const void* p, long long i, int is64) {
    return is64 ? (int)((const long long*)p)[i] : ((const int*)p)[i];
}

// ---------------- dtype probe ----------------
// int64 data with nonnegative values < 2^31: odd 32-bit words are all zero.
// int32 data: odd words are random indices (zero with prob ~1e-5 per word).
#define PROBE_WORDS 2048
#define PROBE_THRESH 900
__global__ void detect_kernel(const int* __restrict__ ei_w,
                              const int* __restrict__ batch_w) {
    if (threadIdx.x != 0 || blockIdx.x != 0) return;
    int z = 0;
    for (int i = 1; i < PROBE_WORDS; i += 2) if (ei_w[i] == 0) z++;
    g_is64_ei = (z > PROBE_THRESH) ? 1 : 0;
    // probe batch in its middle region: sorted graph ids there are ~NG/2 (nonzero)
    z = 0;
    const int base = NN / 2;   // in-bounds for both dtype interpretations
    for (int i = 1; i < PROBE_WORDS; i += 2) if (batch_w[base + i] == 0) z++;
    g_is64_batch = (z > PROBE_THRESH) ? 1 : 0;
}

// ---------------- pre-pass kernels ----------------
__global__ void zero_kernel() {
    int idx = blockIdx.x * blockDim.x + threadIdx.x;
    if (idx < NN) g_cnt[idx] = 0;
    if (idx < NG * DD) g_pool[idx] = 0.f;
    if (idx < NG) g_pcnt[idx] = 0.f;
}

__global__ void hist_kernel(const void* __restrict__ ei) {
    int e = blockIdx.x * blockDim.x + threadIdx.x;
    if (e >= NE) return;
    int d = load_idx(ei, (long long)NE + e, g_is64_ei);
    atomicAdd(&g_cnt[d], 1);
}

// single-block exclusive scan over g_cnt -> g_rowptr; also dinv and fill cursors
__global__ void scan_kernel() {
    __shared__ int warpsums[32];
    int tid = threadIdx.x, lane = tid & 31, wid = tid >> 5;
    int running = 0;
    for (int base = 0; base < NN; base += 1024) {
        int idx = base + tid;
        int v = (idx < NN) ? g_cnt[idx] : 0;
        int x = v;
        #pragma unroll
        for (int o = 1; o < 32; o <<= 1) {
            int y = __shfl_up_sync(0xFFFFFFFFu, x, o);
            if (lane >= o) x += y;
        }
        if (lane == 31) warpsums[wid] = x;
        __syncthreads();
        if (wid == 0) {
            int s = warpsums[lane];
            #pragma unroll
            for (int o = 1; o < 32; o <<= 1) {
                int y = __shfl_up_sync(0xFFFFFFFFu, s, o);
                if (lane >= o) s += y;
            }
            warpsums[lane] = s;
        }
        __syncthreads();
        int excl = x - v + (wid > 0 ? warpsums[wid - 1] : 0) + running;
        if (idx < NN) {
            g_rowptr[idx] = excl;
            g_dinv[idx] = rsqrtf((float)(v + 1));  // deg includes self-loop
            g_cnt[idx] = excl;                     // fill cursor
        }
        running += warpsums[31];
        __syncthreads();
    }
    if (tid == 0) g_rowptr[NN] = running;
}

__global__ void fill_kernel(const void* __restrict__ ei) {
    int e = blockIdx.x * blockDim.x + threadIdx.x;
    if (e >= NE) return;
    int is64 = g_is64_ei;
    int s = load_idx(ei, e, is64);
    int d = load_idx(ei, (long long)NE + e, is64);
    int pos = atomicAdd(&g_cnt[d], 1);
    g_col[pos] = s;
    g_w[pos] = g_dinv[s] * g_dinv[d];
}

// ---------------- per-layer kernels ----------------
// T = f(A) @ W + b   (f = leaky for layer>0; BN affine pre-folded into W,b)
__global__ __launch_bounds__(256) void gemm_kernel(const float* __restrict__ x0,
                                                   const float* __restrict__ W0,
                                                   const float* __restrict__ b0,
                                                   int layer) {
    const float* __restrict__ A    = layer ? g_AGG : x0;
    const float* __restrict__ W    = layer ? g_Wf  : W0;
    const float* __restrict__ bias = layer ? g_bf  : b0;

    __shared__ __align__(16) float sA[16][132];
    __shared__ __align__(16) float sW[16][128];
    __shared__ float sB[128];
    int tid = threadIdx.x;
    if (blockIdx.x == 0 && tid < 128) { g_sum[tid] = 0.0; g_sq[tid] = 0.0; }
    if (tid < 128) sB[tid] = bias[tid];

    int row0 = blockIdx.x * 128;
    int tx = tid & 15, ty = tid >> 4;
    float acc[8][8];
    #pragma unroll
    for (int i = 0; i < 8; i++)
        #pragma unroll
        for (int j = 0; j < 8; j++) acc[i][j] = 0.f;

    const float4* W4 = (const float4*)W;
    for (int k0 = 0; k0 < 128; k0 += 16) {
        #pragma unroll
        for (int t = 0; t < 2; t++) {
            int idx = tid + t * 256;
            ((float4*)&sW[0][0])[idx] = W4[k0 * 32 + idx];
        }
        #pragma unroll
        for (int t = 0; t < 2; t++) {
            int idx = tid + t * 256;
            int r = idx >> 2, q = idx & 3;
            int row = row0 + r;
            float4 v = make_float4(0.f, 0.f, 0.f, 0.f);
            if (row < NN) v = *((const float4*)(A + (size_t)row * 128 + k0 + q * 4));
            if (layer) {
                v.x = leaky_f(v.x); v.y = leaky_f(v.y);
                v.z = leaky_f(v.z); v.w = leaky_f(v.w);
            }
            sA[q * 4 + 0][r] = v.x; sA[q * 4 + 1][r] = v.y;
            sA[q * 4 + 2][r] = v.z; sA[q * 4 + 3][r] = v.w;
        }
        __syncthreads();
        #pragma unroll
        for (int kk = 0; kk < 16; kk++) {
            float a[8], b[8];
            *(float4*)&a[0] = *(const float4*)&sA[kk][ty * 8];
            *(float4*)&a[4] = *(const float4*)&sA[kk][ty * 8 + 4];
            *(float4*)&b[0] = *(const float4*)&sW[kk][tx * 8];
            *(float4*)&b[4] = *(const float4*)&sW[kk][tx * 8 + 4];
            #pragma unroll
            for (int i = 0; i < 8; i++)
                #pragma unroll
                for (int j = 0; j < 8; j++) acc[i][j] += a[i] * b[j];
        }
        __syncthreads();
    }
    #pragma unroll
    for (int i = 0; i < 8; i++) {
        int row = row0 + ty * 8 + i;
        if (row < NN) {
            float4 o0 = make_float4(acc[i][0] + sB[tx * 8 + 0], acc[i][1] + sB[tx * 8 + 1],
                                    acc[i][2] + sB[tx * 8 + 2], acc[i][3] + sB[tx * 8 + 3]);
            float4 o1 = make_float4(acc[i][4] + sB[tx * 8 + 4], acc[i][5] + sB[tx * 8 + 5],
                                    acc[i][6] + sB[tx * 8 + 6], acc[i][7] + sB[tx * 8 + 7]);
            *((float4*)(g_T + (size_t)row * 128 + tx * 8))     = o0;
            *((float4*)(g_T + (size_t)row * 128 + tx * 8 + 4)) = o1;
        }
    }
}

// AGG[v] = dinv[v]^2 * T[v] + sum_{e: dst=v} w[e] * T[col[e]]   (one warp per node)
__global__ void gather_kernel() {
    int gtid = blockIdx.x * blockDim.x + threadIdx.x;
    int v = gtid >> 5;
    int lane = gtid & 31;
    if (v >= NN) return;
    int beg = g_rowptr[v], end = g_rowptr[v + 1];
    float dv = g_dinv[v];
    const float4* T4 = (const float4*)g_T;
    float4 acc = T4[(size_t)v * 32 + lane];
    float s2 = dv * dv;
    acc.x *= s2; acc.y *= s2; acc.z *= s2; acc.w *= s2;
    int i = beg;
    for (; i + 4 <= end; i += 4) {
        int s0 = g_col[i], s1 = g_col[i + 1], s2i = g_col[i + 2], s3 = g_col[i + 3];
        float w0 = g_w[i], w1 = g_w[i + 1], w2 = g_w[i + 2], w3 = g_w[i + 3];
        float4 t0 = T4[(size_t)s0 * 32 + lane];
        float4 t1 = T4[(size_t)s1 * 32 + lane];
        float4 t2 = T4[(size_t)s2i * 32 + lane];
        float4 t3 = T4[(size_t)s3 * 32 + lane];
        acc.x += w0 * t0.x + w1 * t1.x + w2 * t2.x + w3 * t3.x;
        acc.y += w0 * t0.y + w1 * t1.y + w2 * t2.y + w3 * t3.y;
        acc.z += w0 * t0.z + w1 * t1.z + w2 * t2.z + w3 * t3.z;
        acc.w += w0 * t0.w + w1 * t1.w + w2 * t2.w + w3 * t3.w;
    }
    for (; i < end; i++) {
        int s = g_col[i]; float wt = g_w[i];
        float4 t = T4[(size_t)s * 32 + lane];
        acc.x += wt * t.x; acc.y += wt * t.y; acc.z += wt * t.z; acc.w += wt * t.w;
    }
    ((float4*)g_AGG)[(size_t)v * 32 + lane] = acc;
}

// per-channel sum / sumsq of leaky(AGG)
__global__ void stats_kernel() {
    int c = threadIdx.x & 127;
    int half = threadIdx.x >> 7;
    float s = 0.f, q = 0.f;
    for (int r = blockIdx.x * 2 + half; r < NN; r += gridDim.x * 2) {
        float v = leaky_f(g_AGG[(size_t)r * 128 + c]);
        s += v; q += v * v;
    }
    __shared__ float ss[128], qq[128];
    if (half == 1) { ss[c] = s; qq[c] = q; }
    __syncthreads();
    if (half == 0) {
        atomicAdd(&g_sum[c], (double)(s + ss[c]));
        atomicAdd(&g_sq[c], (double)(q + qq[c]));
    }
}

// fold BN affine of layer i into next layer's W,b (or keep a,c for last layer)
__global__ void fold_kernel(const float* __restrict__ Wnext,
                            const float* __restrict__ bnext,
                            const float* __restrict__ gamma,
                            const float* __restrict__ beta,
                            int isLast) {
    int j = threadIdx.x;
    float mu = (float)(g_sum[j] / (double)NN);
    float var = (float)(g_sq[j] / (double)NN - (double)mu * (double)mu);
    var = fmaxf(var, 0.f);
    float a = gamma[j] * rsqrtf(var + BN_EPS);
    float cc = beta[j] - mu * a;
    __shared__ float sa[128], sc[128];
    sa[j] = a; sc[j] = cc;
    __syncthreads();
    if (isLast) { g_a[j] = a; g_c[j] = cc; return; }
    float bacc = bnext[j];
    for (int k = 0; k < 128; k++) {
        float wkj = Wnext[k * 128 + j];
        g_Wf[k * 128 + j] = sa[k] * wkj;
        bacc += sc[k] * wkj;
    }
    g_bf[j] = bacc;
}

// run-length pooling over sorted batch ids: one thread per channel, 128 rows/block
__global__ void pool_kernel(const void* __restrict__ batch) {
    int c = threadIdx.x;
    int r0 = blockIdx.x * 128;
    int rend = min(r0 + 128, NN);
    int is64 = g_is64_batch;
    float a = g_a[c], cc = g_c[c];
    int curg = load_idx(batch, r0, is64);
    float acc = 0.f; int run = 0;
    for (int r = r0; r < rend; r++) {
        int g = load_idx(batch, r, is64);
        if (g != curg) {
            atomicAdd(&g_pool[curg * 128 + c], acc);
            if (c == 0) atomicAdd(&g_pcnt[curg], (float)run);
            acc = 0.f; run = 0; curg = g;
        }
        float v = leaky_f(g_AGG[(size_t)r * 128 + c]);
        acc += v * a + cc;
        run++;
    }
    atomicAdd(&g_pool[curg * 128 + c], acc);
    if (c == 0) atomicAdd(&g_pcnt[curg], (float)run);
}

__global__ void final_kernel(float* __restrict__ out) {
    int idx = blockIdx.x * blockDim.x + threadIdx.x;
    if (idx < NG * DD) {
        int g = idx >> 7;
        out[idx] = g_pool[idx] / fmaxf(g_pcnt[g], 1.f);
    }
}

// ---------------- launch ----------------
extern "C" void kernel_launch(void* const* d_in, const int* in_sizes, int n_in,
                              void* d_out, int out_size) {
    const float* x = (const float*)d_in[0];
    const void* ei = d_in[1];                 // [2, NE] int32 or int64
    const void* batch = d_in[2];              // [NN]    int32 or int64
    const float* Ws = (const float*)d_in[3];  // [NL, DD, DD]
    const float* bs = (const float*)d_in[4];
    const float* gm = (const float*)d_in[5];
    const float* bt = (const float*)d_in[6];
    float* out = (float*)d_out;

    detect_kernel<<<1, 32>>>((const int*)ei, (const int*)batch);
    zero_kernel<<<(NN + 255) / 256, 256>>>();
    hist_kernel<<<(NE + 255) / 256, 256>>>(ei);
    scan_kernel<<<1, 1024>>>();
    fill_kernel<<<(NE + 255) / 256, 256>>>(ei);

    for (int i = 0; i < NL; i++) {
        gemm_kernel<<<(NN + 127) / 128, 256>>>(x, Ws + (size_t)i * DD * DD,
                                               bs + (size_t)i * DD, i);
        gather_kernel<<<(NN * 32 + 255) / 256, 256>>>();
        stats_kernel<<<512, 256>>>();
        int nxt = (i + 1 < NL) ? (i + 1) : 0;  // pointer unused when isLast
        fold_kernel<<<1, 128>>>(Ws + (size_t)nxt * DD * DD, bs + (size_t)nxt * DD,
                                gm + (size_t)i * DD, bt + (size_t)i * DD,
                                (i == NL - 1) ? 1 : 0);
    }
    pool_kernel<<<(NN + 127) / 128, 128>>>(batch);
    final_kernel<<<(NG * DD + 255) / 256, 256>>>(out);
}

// round 5
// speedup vs baseline: 1.1925x; 1.1925x over previous
#include <cuda_runtime.h>

#define NN 100000
#define NE 1600000
#define DD 128
#define NG 64
#define NL 7
#define LEAKY 0.01f
#define BN_EPS 1e-5f

#define SCAN_BLK 256
#define SCAN_NB ((NN + SCAN_BLK - 1) / SCAN_BLK)   // 391
#define GATHER_BLOCKS 592                           // 4 per SM

// ---------------- scratch (static device globals; no allocation) ----------------
__device__ __align__(16) float  g_T[(size_t)NN * DD];     // GEMM output (messages source)
__device__ __align__(16) float  g_AGG[(size_t)NN * DD];   // aggregated (pre-activation)
__device__ int    g_cnt[NN];                // histogram, then reused as fill cursor
__device__ int    g_rowptr[NN + 1];
__device__ int    g_bsum[SCAN_NB];          // per-block sums for scan
__device__ int    g_boff[SCAN_NB];          // exclusive offsets of block sums
__device__ int    g_col[NE];
__device__ float  g_w[NE];
__device__ float  g_dinv[NN];
__device__ double g_sum[DD], g_sq[DD];
__device__ __align__(16) float  g_Wf[DD * DD];            // BN-folded weights for next layer
__device__ float  g_bf[DD];
__device__ float  g_a[DD], g_c[DD];         // last-layer BN affine
__device__ float  g_pool[NG * DD];
__device__ float  g_pcnt[NG];
__device__ int    g_is64_ei, g_is64_batch;  // input index dtype flags

__device__ __forceinline__ float leaky_f(float v) { return v > 0.f ? v : LEAKY * v; }

__device__ __forceinline__ int load_idx(const void* p, long long i, int is64) {
    return is64 ? (int)((const long long*)p)[i] : ((const int*)p)[i];
}

// ---------------- dtype probe (warp-parallel) ----------------
// int64 data with nonnegative values < 2^31: odd 32-bit words are all zero.
// int32 data: odd words are random indices (zero with prob ~1e-5 per word).
#define PROBE_WORDS 2048
#define PROBE_THRESH 900
__global__ void detect_kernel(const int* __restrict__ ei_w,
                              const int* __restrict__ batch_w) {
    int lane = threadIdx.x & 31;
    int z = 0;
    for (int i = 1 + 2 * lane; i < PROBE_WORDS; i += 64)
        if (ei_w[i] == 0) z++;
    #pragma unroll
    for (int o = 16; o > 0; o >>= 1) z += __shfl_xor_sync(0xFFFFFFFFu, z, o);
    if (lane == 0) g_is64_ei = (z > PROBE_THRESH / 2) ? 1 : 0;  // 1024 odd words probed
    int z2 = 0;
    const int base = NN / 2;   // sorted graph ids here are ~NG/2 (nonzero) if int32
    for (int i = 1 + 2 * lane; i < PROBE_WORDS; i += 64)
        if (batch_w[base + i] == 0) z2++;
    #pragma unroll
    for (int o = 16; o > 0; o >>= 1) z2 += __shfl_xor_sync(0xFFFFFFFFu, z2, o);
    if (lane == 0) g_is64_batch = (z2 > PROBE_THRESH / 2) ? 1 : 0;
}

// ---------------- pre-pass kernels ----------------
__global__ void zero_kernel() {
    int idx = blockIdx.x * blockDim.x + threadIdx.x;
    if (idx < NN) g_cnt[idx] = 0;
    if (idx < NG * DD) g_pool[idx] = 0.f;
    if (idx < NG) g_pcnt[idx] = 0.f;
}

__global__ void hist_kernel(const void* __restrict__ ei) {
    int e = blockIdx.x * blockDim.x + threadIdx.x;
    if (e >= NE) return;
    int d = load_idx(ei, (long long)NE + e, g_is64_ei);
    atomicAdd(&g_cnt[d], 1);
}

// ---- multi-block scan: pass 1 (block-local exclusive scan + block sum + dinv) ----
__global__ void scan1_kernel() {
    __shared__ int wsum[8];
    int idx = blockIdx.x * SCAN_BLK + threadIdx.x;
    int lane = threadIdx.x & 31, wid = threadIdx.x >> 5;
    int v = (idx < NN) ? g_cnt[idx] : 0;
    int x = v;
    #pragma unroll
    for (int o = 1; o < 32; o <<= 1) {
        int y = __shfl_up_sync(0xFFFFFFFFu, x, o);
        if (lane >= o) x += y;
    }
    if (lane == 31) wsum[wid] = x;
    __syncthreads();
    if (wid == 0 && lane < 8) {
        int s = wsum[lane];
        #pragma unroll
        for (int o = 1; o < 8; o <<= 1) {
            int y = __shfl_up_sync(0xFFu, s, o);
            if (lane >= o) s += y;
        }
        wsum[lane] = s;
    }
    __syncthreads();
    int excl = x - v + (wid > 0 ? wsum[wid - 1] : 0);
    if (idx < NN) {
        g_rowptr[idx] = excl;                  // block-local for now
        g_dinv[idx] = rsqrtf((float)(v + 1));  // deg includes self-loop
    }
    if (threadIdx.x == SCAN_BLK - 1) g_bsum[blockIdx.x] = excl + v;
}

// ---- pass 2: single block scans 391 block sums (exclusive) ----
__global__ void scan2_kernel() {
    __shared__ int sh[SCAN_NB];
    int tid = threadIdx.x;
    if (tid < SCAN_NB) sh[tid] = g_bsum[tid];
    __syncthreads();
    // Hillis-Steele inclusive scan in shared (512 threads cover 391)
    for (int o = 1; o < SCAN_NB; o <<= 1) {
        int val = 0;
        if (tid < SCAN_NB && tid >= o) val = sh[tid - o];
        __syncthreads();
        if (tid < SCAN_NB) sh[tid] += val;
        __syncthreads();
    }
    if (tid < SCAN_NB) g_boff[tid] = (tid > 0) ? sh[tid - 1] : 0;
    if (tid == 0) g_rowptr[NN] = sh[SCAN_NB - 1];
}

// ---- pass 3: add block offsets, init fill cursors ----
__global__ void scan3_kernel() {
    int idx = blockIdx.x * SCAN_BLK + threadIdx.x;
    if (idx >= NN) return;
    int r = g_rowptr[idx] + g_boff[blockIdx.x];
    g_rowptr[idx] = r;
    g_cnt[idx] = r;   // fill cursor
}

__global__ void fill_kernel(const void* __restrict__ ei) {
    int e = blockIdx.x * blockDim.x + threadIdx.x;
    if (e >= NE) return;
    int is64 = g_is64_ei;
    int s = load_idx(ei, e, is64);
    int d = load_idx(ei, (long long)NE + e, is64);
    int pos = atomicAdd(&g_cnt[d], 1);
    g_col[pos] = s;
    g_w[pos] = g_dinv[s] * g_dinv[d];
}

// ---------------- per-layer kernels ----------------
// T = f(A) @ W + b   (f = leaky for layer>0; BN affine pre-folded into W,b)
// Also zeroes the channel-stat accumulators for this layer (block 0).
__global__ __launch_bounds__(256) void gemm_kernel(const float* __restrict__ x0,
                                                   const float* __restrict__ W0,
                                                   const float* __restrict__ b0,
                                                   int layer) {
    const float* __restrict__ A    = layer ? g_AGG : x0;
    const float* __restrict__ W    = layer ? g_Wf  : W0;
    const float* __restrict__ bias = layer ? g_bf  : b0;

    __shared__ __align__(16) float sA[16][132];
    __shared__ __align__(16) float sW[16][128];
    __shared__ float sB[128];
    int tid = threadIdx.x;
    if (blockIdx.x == 0 && tid < 128) { g_sum[tid] = 0.0; g_sq[tid] = 0.0; }
    if (tid < 128) sB[tid] = bias[tid];

    int row0 = blockIdx.x * 128;
    int tx = tid & 15, ty = tid >> 4;
    float acc[8][8];
    #pragma unroll
    for (int i = 0; i < 8; i++)
        #pragma unroll
        for (int j = 0; j < 8; j++) acc[i][j] = 0.f;

    const float4* W4 = (const float4*)W;
    for (int k0 = 0; k0 < 128; k0 += 16) {
        #pragma unroll
        for (int t = 0; t < 2; t++) {
            int idx = tid + t * 256;
            ((float4*)&sW[0][0])[idx] = W4[k0 * 32 + idx];
        }
        #pragma unroll
        for (int t = 0; t < 2; t++) {
            int idx = tid + t * 256;
            int r = idx >> 2, q = idx & 3;
            int row = row0 + r;
            float4 v = make_float4(0.f, 0.f, 0.f, 0.f);
            if (row < NN) v = *((const float4*)(A + (size_t)row * 128 + k0 + q * 4));
            if (layer) {
                v.x = leaky_f(v.x); v.y = leaky_f(v.y);
                v.z = leaky_f(v.z); v.w = leaky_f(v.w);
            }
            sA[q * 4 + 0][r] = v.x; sA[q * 4 + 1][r] = v.y;
            sA[q * 4 + 2][r] = v.z; sA[q * 4 + 3][r] = v.w;
        }
        __syncthreads();
        #pragma unroll
        for (int kk = 0; kk < 16; kk++) {
            float a[8], b[8];
            *(float4*)&a[0] = *(const float4*)&sA[kk][ty * 8];
            *(float4*)&a[4] = *(const float4*)&sA[kk][ty * 8 + 4];
            *(float4*)&b[0] = *(const float4*)&sW[kk][tx * 8];
            *(float4*)&b[4] = *(const float4*)&sW[kk][tx * 8 + 4];
            #pragma unroll
            for (int i = 0; i < 8; i++)
                #pragma unroll
                for (int j = 0; j < 8; j++) acc[i][j] += a[i] * b[j];
        }
        __syncthreads();
    }
    #pragma unroll
    for (int i = 0; i < 8; i++) {
        int row = row0 + ty * 8 + i;
        if (row < NN) {
            float4 o0 = make_float4(acc[i][0] + sB[tx * 8 + 0], acc[i][1] + sB[tx * 8 + 1],
                                    acc[i][2] + sB[tx * 8 + 2], acc[i][3] + sB[tx * 8 + 3]);
            float4 o1 = make_float4(acc[i][4] + sB[tx * 8 + 4], acc[i][5] + sB[tx * 8 + 5],
                                    acc[i][6] + sB[tx * 8 + 6], acc[i][7] + sB[tx * 8 + 7]);
            *((float4*)(g_T + (size_t)row * 128 + tx * 8))     = o0;
            *((float4*)(g_T + (size_t)row * 128 + tx * 8 + 4)) = o1;
        }
    }
}

// Persistent gather + fused channel stats.
// AGG[v] = dinv[v]^2 * T[v] + sum_{e: dst=v} w[e] * T[col[e]]   (one warp per node,
// grid-stride). Each thread accumulates per-channel sum/sumsq of leaky(AGG) for its
// 4 channels in registers, then block-reduce -> global double atomics (once/block).
__global__ __launch_bounds__(256) void gather_kernel() {
    int lane = threadIdx.x & 31;
    int gwarp = blockIdx.x * 8 + (threadIdx.x >> 5);
    const int nwarps = GATHER_BLOCKS * 8;
    const float4* T4 = (const float4*)g_T;

    float4 ssum = make_float4(0.f, 0.f, 0.f, 0.f);
    float4 ssq  = make_float4(0.f, 0.f, 0.f, 0.f);

    for (int v = gwarp; v < NN; v += nwarps) {
        int beg = g_rowptr[v], end = g_rowptr[v + 1];
        float dv = g_dinv[v];
        float4 acc = T4[(size_t)v * 32 + lane];
        float s2 = dv * dv;
        acc.x *= s2; acc.y *= s2; acc.z *= s2; acc.w *= s2;
        int i = beg;
        for (; i + 4 <= end; i += 4) {
            int s0 = g_col[i], s1 = g_col[i + 1], s2i = g_col[i + 2], s3 = g_col[i + 3];
            float w0 = g_w[i], w1 = g_w[i + 1], w2 = g_w[i + 2], w3 = g_w[i + 3];
            float4 t0 = T4[(size_t)s0 * 32 + lane];
            float4 t1 = T4[(size_t)s1 * 32 + lane];
            float4 t2 = T4[(size_t)s2i * 32 + lane];
            float4 t3 = T4[(size_t)s3 * 32 + lane];
            acc.x += w0 * t0.x + w1 * t1.x + w2 * t2.x + w3 * t3.x;
            acc.y += w0 * t0.y + w1 * t1.y + w2 * t2.y + w3 * t3.y;
            acc.z += w0 * t0.z + w1 * t1.z + w2 * t2.z + w3 * t3.z;
            acc.w += w0 * t0.w + w1 * t1.w + w2 * t2.w + w3 * t3.w;
        }
        for (; i < end; i++) {
            int s = g_col[i]; float wt = g_w[i];
            float4 t = T4[(size_t)s * 32 + lane];
            acc.x += wt * t.x; acc.y += wt * t.y; acc.z += wt * t.z; acc.w += wt * t.w;
        }
        ((float4*)g_AGG)[(size_t)v * 32 + lane] = acc;
        float lx = leaky_f(acc.x), ly = leaky_f(acc.y);
        float lz = leaky_f(acc.z), lw = leaky_f(acc.w);
        ssum.x += lx; ssum.y += ly; ssum.z += lz; ssum.w += lw;
        ssq.x += lx * lx; ssq.y += ly * ly; ssq.z += lz * lz; ssq.w += lw * lw;
    }

    __shared__ float bsum[128], bsq[128];
    if (threadIdx.x < 128) { bsum[threadIdx.x] = 0.f; bsq[threadIdx.x] = 0.f; }
    __syncthreads();
    int c0 = lane * 4;
    atomicAdd(&bsum[c0 + 0], ssum.x); atomicAdd(&bsq[c0 + 0], ssq.x);
    atomicAdd(&bsum[c0 + 1], ssum.y); atomicAdd(&bsq[c0 + 1], ssq.y);
    atomicAdd(&bsum[c0 + 2], ssum.z); atomicAdd(&bsq[c0 + 2], ssq.z);
    atomicAdd(&bsum[c0 + 3], ssum.w); atomicAdd(&bsq[c0 + 3], ssq.w);
    __syncthreads();
    if (threadIdx.x < 128) {
        atomicAdd(&g_sum[threadIdx.x], (double)bsum[threadIdx.x]);
        atomicAdd(&g_sq[threadIdx.x], (double)bsq[threadIdx.x]);
    }
}

// fold BN affine of layer i into next layer's W,b (or keep a,c for last layer)
__global__ void fold_kernel(const float* __restrict__ Wnext,
                            const float* __restrict__ bnext,
                            const float* __restrict__ gamma,
                            const float* __restrict__ beta,
                            int isLast) {
    int j = threadIdx.x;
    float mu = (float)(g_sum[j] / (double)NN);
    float var = (float)(g_sq[j] / (double)NN - (double)mu * (double)mu);
    var = fmaxf(var, 0.f);
    float a = gamma[j] * rsqrtf(var + BN_EPS);
    float cc = beta[j] - mu * a;
    __shared__ float sa[128], sc[128];
    sa[j] = a; sc[j] = cc;
    __syncthreads();
    if (isLast) { g_a[j] = a; g_c[j] = cc; return; }
    float bacc = bnext[j];
    for (int k = 0; k < 128; k++) {
        float wkj = Wnext[k * 128 + j];
        g_Wf[k * 128 + j] = sa[k] * wkj;
        bacc += sc[k] * wkj;
    }
    g_bf[j] = bacc;
}

// run-length pooling over sorted batch ids: one thread per channel, 128 rows/block
__global__ void pool_kernel(const void* __restrict__ batch) {
    int c = threadIdx.x;
    int r0 = blockIdx.x * 128;
    int rend = min(r0 + 128, NN);
    int is64 = g_is64_batch;
    float a = g_a[c], cc = g_c[c];
    int curg = load_idx(batch, r0, is64);
    float acc = 0.f; int run = 0;
    for (int r = r0; r < rend; r++) {
        int g = load_idx(batch, r, is64);
        if (g != curg) {
            atomicAdd(&g_pool[curg * 128 + c], acc);
            if (c == 0) atomicAdd(&g_pcnt[curg], (float)run);
            acc = 0.f; run = 0; curg = g;
        }
        float v = leaky_f(g_AGG[(size_t)r * 128 + c]);
        acc += v * a + cc;
        run++;
    }
    atomicAdd(&g_pool[curg * 128 + c], acc);
    if (c == 0) atomicAdd(&g_pcnt[curg], (float)run);
}

__global__ void final_kernel(float* __restrict__ out) {
    int idx = blockIdx.x * blockDim.x + threadIdx.x;
    if (idx < NG * DD) {
        int g = idx >> 7;
        out[idx] = g_pool[idx] / fmaxf(g_pcnt[g], 1.f);
    }
}

// ---------------- launch ----------------
extern "C" void kernel_launch(void* const* d_in, const int* in_sizes, int n_in,
                              void* d_out, int out_size) {
    const float* x = (const float*)d_in[0];
    const void* ei = d_in[1];                 // [2, NE] int32 or int64
    const void* batch = d_in[2];              // [NN]    int32 or int64
    const float* Ws = (const float*)d_in[3];  // [NL, DD, DD]
    const float* bs = (const float*)d_in[4];
    const float* gm = (const float*)d_in[5];
    const float* bt = (const float*)d_in[6];
    float* out = (float*)d_out;

    detect_kernel<<<1, 32>>>((const int*)ei, (const int*)batch);
    zero_kernel<<<(NN + 255) / 256, 256>>>();
    hist_kernel<<<(NE + 255) / 256, 256>>>(ei);
    scan1_kernel<<<SCAN_NB, SCAN_BLK>>>();
    scan2_kernel<<<1, 512>>>();
    scan3_kernel<<<SCAN_NB, SCAN_BLK>>>();
    fill_kernel<<<(NE + 255) / 256, 256>>>(ei);

    for (int i = 0; i < NL; i++) {
        gemm_kernel<<<(NN + 127) / 128, 256>>>(x, Ws + (size_t)i * DD * DD,
                                               bs + (size_t)i * DD, i);
        gather_kernel<<<GATHER_BLOCKS, 256>>>();
        int nxt = (i + 1 < NL) ? (i + 1) : 0;  // pointer unused when isLast
        fold_kernel<<<1, 128>>>(Ws + (size_t)nxt * DD * DD, bs + (size_t)nxt * DD,
                                gm + (size_t)i * DD, bt + (size_t)i * DD,
                                (i == NL - 1) ? 1 : 0);
    }
    pool_kernel<<<(NN + 127) / 128, 128>>>(batch);
    final_kernel<<<(NG * DD + 255) / 256, 256>>>(out);
}